// round 5
// baseline (speedup 1.0000x reference)
#include <cuda_runtime.h>
#include <math.h>
#include <stdint.h>

#define BB 32
#define HID 512
#define CTXD 512
#define EMBD 256
#define ATTN 256
#define VOC 5000
#define TT 160
#define NG 2560
#define KST 1024
#define NA 257
#define GB 128           // persistent grid blocks

// ---------------- device scratch (static; no allocation) ----------------
__device__ float g_ctx_embed[BB*ATTN*CTXD];
__device__ float g_xproj[TT*BB*NG];
__device__ float g_Xemb[TT*BB*EMBD];
__device__ float g_Wpack[KST*NG];
__device__ float g_WxPack[EMBD*NG];
__device__ float g_biasPack[NG];
__device__ float g_A[BB*KST];          // [prev_out(512) | h(512)]
__device__ float g_c[BB*HID];
__device__ float g_gp[32*BB*NG];       // gates partials: 32 splitK buckets
__device__ float g_p3[2*16*BB*HID];    // fr0@Wfr, h@Who partials
__device__ float g_p4[2*16*BB*HID];    // fr@Wfre, hol@Whoe partials
__device__ float g_p7[16*BB*HID];      // visph@Watt partials
__device__ float g_fr0[BB*HID];
__device__ float g_fr[BB*HID];
__device__ float g_hol[BB*HID];
__device__ float g_fre[BB*HID];
__device__ float g_hoe[BB*HID];
__device__ float g_scores[BB*NA];
__device__ float g_visph[BB*HID];
__device__ float g_outh[TT*BB*HID];
__device__ float g_logits[TT*BB*VOC];

// grid barrier state
__device__ volatile unsigned g_barg;
__device__ unsigned g_barc;

__device__ __forceinline__ float sigf(float x){ return 1.f/(1.f+expf(-x)); }
__device__ __forceinline__ float tanha(float x){ float y; asm("tanh.approx.f32 %0, %1;" : "=f"(y) : "f"(x)); return y; }

// ---------------- setup kernels ----------------
__global__ void k_init(){
    int i = blockIdx.x*256 + threadIdx.x;
    if (i < BB*KST) g_A[i] = 0.f;
    if (i < BB*HID) g_c[i] = 0.f;
}

__global__ void k_packW(const float* __restrict__ Wih, const float* __restrict__ Whh,
                        const float* __restrict__ Wi2h, const float* __restrict__ Wh2h){
    int idx = blockIdx.x*256 + threadIdx.x;   // exactly KST*NG
    int k = idx / NG, n = idx % NG;
    float v;
    if (k < HID) v = (n < 4*HID) ? Wih[(size_t)(EMBD+k)*4*HID + n] : Wi2h[(size_t)(EMBD+k)*HID + (n-4*HID)];
    else         v = (n < 4*HID) ? Whh[(size_t)(k-HID)*4*HID + n]  : Wh2h[(size_t)(k-HID)*HID + (n-4*HID)];
    g_Wpack[idx] = v;
}

__global__ void k_packX(const float* __restrict__ Wih, const float* __restrict__ Wi2h,
                        const float* __restrict__ bih, const float* __restrict__ bhh,
                        const float* __restrict__ bi2h, const float* __restrict__ bh2h){
    int idx = blockIdx.x*256 + threadIdx.x;   // exactly EMBD*NG
    if (idx < NG)
        g_biasPack[idx] = (idx < 4*HID) ? (bih[idx] + bhh[idx]) : (bi2h[idx-4*HID] + bh2h[idx-4*HID]);
    int k = idx / NG, n = idx % NG;
    g_WxPack[idx] = (n < 4*HID) ? Wih[(size_t)k*4*HID + n] : Wi2h[(size_t)k*HID + (n-4*HID)];
}

__global__ void k_gather(const int* __restrict__ seq, const float* __restrict__ embed){
    int idx = blockIdx.x*256 + threadIdx.x;   // exactly TT*BB*EMBD
    int e = idx & (EMBD-1);
    int r = idx >> 8;
    int t = r >> 5, b = r & 31;
    int tok = seq[b*161 + t];
    g_Xemb[idx] = embed[(size_t)tok*EMBD + e];
}

// ---------------- big GEMM: 64x64 tile fp32 (pre/post processing) ----------------
__global__ void __launch_bounds__(256) gemm_big(int mode, const float* __restrict__ Aext,
                        const float* __restrict__ Wext, const float* __restrict__ bext,
                        int N, int K, int act){
    const float* A; const float* W; const float* bias; float* C; int lda, ldw, ldc;
    if (mode == 0){ A=Aext;   W=Wext;     bias=bext;      C=g_ctx_embed; lda=512; ldw=512;  ldc=512; }
    else if (mode==1){ A=g_Xemb; W=g_WxPack; bias=g_biasPack; C=g_xproj; lda=256; ldw=NG;   ldc=NG;  }
    else            { A=g_outh;  W=Wext;     bias=bext;      C=g_logits; lda=512; ldw=VOC;  ldc=VOC; }

    __shared__ float sAT[32][68];
    __shared__ float sW[32][68];
    int tid = threadIdx.x;
    int row0 = blockIdx.y*64, col0 = blockIdx.x*64;
    int w = tid>>5, l = tid&31;
    int m4 = 32*(w&1) + 4*(l&7);
    int n4 = 16*(w>>1) + 4*(l>>3);
    float acc[4][4];
#pragma unroll
    for (int i=0;i<4;i++)
#pragma unroll
        for (int j=0;j<4;j++) acc[i][j]=0.f;

    for (int k0=0; k0<K; k0+=32){
#pragma unroll
        for (int rep=0;rep<2;rep++){
            int f = tid + rep*256; int m = f>>3, kq = (f&7)<<2;
            float4 v = *(const float4*)(A + (size_t)(row0+m)*lda + k0 + kq);
            sAT[kq][m]=v.x; sAT[kq+1][m]=v.y; sAT[kq+2][m]=v.z; sAT[kq+3][m]=v.w;
        }
#pragma unroll
        for (int rep=0;rep<2;rep++){
            int f = tid + rep*256; int r = f>>4, cq = (f&15)<<2; int col = col0+cq;
            float4 v = make_float4(0.f,0.f,0.f,0.f);
            if (col < N) v = *(const float4*)(W + (size_t)(k0+r)*ldw + col);
            *(float4*)&sW[r][cq] = v;
        }
        __syncthreads();
#pragma unroll
        for (int kk=0;kk<32;kk++){
            float4 av = *(const float4*)&sAT[kk][m4];
            float4 bv = *(const float4*)&sW[kk][n4];
            acc[0][0]+=av.x*bv.x; acc[0][1]+=av.x*bv.y; acc[0][2]+=av.x*bv.z; acc[0][3]+=av.x*bv.w;
            acc[1][0]+=av.y*bv.x; acc[1][1]+=av.y*bv.y; acc[1][2]+=av.y*bv.z; acc[1][3]+=av.y*bv.w;
            acc[2][0]+=av.z*bv.x; acc[2][1]+=av.z*bv.y; acc[2][2]+=av.z*bv.z; acc[2][3]+=av.z*bv.w;
            acc[3][0]+=av.w*bv.x; acc[3][1]+=av.w*bv.y; acc[3][2]+=av.w*bv.z; acc[3][3]+=av.w*bv.w;
        }
        __syncthreads();
    }
#pragma unroll
    for (int i=0;i<4;i++){
        int r = row0 + m4 + i;
#pragma unroll
        for (int j=0;j<4;j++){
            int c = col0 + n4 + j;
            if (c < N){
                float v = acc[i][j] + (bias ? bias[c] : 0.f);
                if (act == 1) v = fmaxf(v, 0.f);
                C[(size_t)r*ldc + c] = v;
            }
        }
    }
}

// ---------------- persistent loop kernel ----------------
__shared__ float sh[32*36 + 32*128];   // sA[32][36] + sW[32][128] = 21KB (union for all phases)

__device__ __forceinline__ void gridbar(){
    __syncthreads();
    if (threadIdx.x == 0){
        unsigned gen = g_barg;
        __threadfence();
        if (atomicAdd(&g_barc, 1u) == (unsigned)(GB-1)){
            g_barc = 0u;
            __threadfence();
            g_barg = gen + 1u;
        } else {
            while (g_barg == gen) { }
        }
        __threadfence();
    }
    __syncthreads();
}

// One GEMM task: out[0:32, col0:col0+128] (partial) = A[0:32, k0:k0+32] @ W[k0:k0+32, col0:col0+128]
// If stage_base != nullptr, A is materialized on the fly: act(sum of 16 partials [s][32][512] + stage_bias).
__device__ __forceinline__ void gtask(const float* A, int lda,
                                      const float* W, int ldw,
                                      int col0, int k0,
                                      float* out, int ldo,
                                      const float* stage_base, const float* stage_bias, int stage_act){
    float* sA = sh;            // pitch 36
    float* sW = sh + 32*36;    // pitch 128
    int tid = threadIdx.x;
    // stage A (32x32)
    {
        int m = tid>>3, kq = (tid&7)<<2;
        float4 av;
        if (stage_base){
            float4 s = *(const float4*)(stage_bias + k0 + kq);
#pragma unroll
            for (int p=0;p<16;p++){
                const float4 v = *(const float4*)(stage_base + p*(BB*HID) + m*HID + k0 + kq);
                s.x+=v.x; s.y+=v.y; s.z+=v.z; s.w+=v.w;
            }
            if (stage_act == 1){ s.x=fmaxf(s.x,0.f); s.y=fmaxf(s.y,0.f); s.z=fmaxf(s.z,0.f); s.w=fmaxf(s.w,0.f); }
            else if (stage_act == 2){ s.x=tanhf(s.x); s.y=tanhf(s.y); s.z=tanhf(s.z); s.w=tanhf(s.w); }
            av = s;
        } else {
            av = *(const float4*)(A + (size_t)m*lda + k0 + kq);
        }
        *(float4*)&sA[m*36 + kq] = av;
    }
    // stage W (32x128)
#pragma unroll
    for (int rep=0;rep<4;rep++){
        int f = tid + rep*256;            // 0..1023
        int row = f>>5, j4 = f&31;
        float4 v = *(const float4*)(W + (size_t)(k0+row)*ldw + col0 + 4*j4);
        *(float4*)&sW[row*128 + 4*j4] = v;
    }
    __syncthreads();
    int mq = tid>>5, nq = tid&31;
    float acc[4][4];
#pragma unroll
    for (int i=0;i<4;i++)
#pragma unroll
        for (int j=0;j<4;j++) acc[i][j]=0.f;
#pragma unroll
    for (int kk=0;kk<32;kk++){
        float a0 = sA[(4*mq+0)*36 + kk];
        float a1 = sA[(4*mq+1)*36 + kk];
        float a2 = sA[(4*mq+2)*36 + kk];
        float a3 = sA[(4*mq+3)*36 + kk];
        float4 w = *(const float4*)&sW[kk*128 + 4*nq];
        acc[0][0]+=a0*w.x; acc[0][1]+=a0*w.y; acc[0][2]+=a0*w.z; acc[0][3]+=a0*w.w;
        acc[1][0]+=a1*w.x; acc[1][1]+=a1*w.y; acc[1][2]+=a1*w.z; acc[1][3]+=a1*w.w;
        acc[2][0]+=a2*w.x; acc[2][1]+=a2*w.y; acc[2][2]+=a2*w.z; acc[2][3]+=a2*w.w;
        acc[3][0]+=a3*w.x; acc[3][1]+=a3*w.y; acc[3][2]+=a3*w.z; acc[3][3]+=a3*w.w;
    }
    __syncthreads();
#pragma unroll
    for (int i=0;i<4;i++){
        float4 o = make_float4(acc[i][0], acc[i][1], acc[i][2], acc[i][3]);
        *(float4*)(out + (size_t)(4*mq+i)*ldo + col0 + 4*nq) = o;
    }
}

__global__ void __launch_bounds__(256) persist_kernel(
        const float* __restrict__ cnn,
        const float* __restrict__ Wfr,  const float* __restrict__ bfr,
        const float* __restrict__ Who,  const float* __restrict__ bho,
        const float* __restrict__ Wfre, const float* __restrict__ bfre,
        const float* __restrict__ Whoe, const float* __restrict__ bhoe,
        const float* __restrict__ Wa,   const float* __restrict__ ba,
        const float* __restrict__ Watt, const float* __restrict__ batt){
    int tid = threadIdx.x;
    int blk = blockIdx.x;

    for (int t=0; t<TT; t++){
        // ---- P1: gates partials: 640 tasks (ks 0..31 x nt 0..19)
        for (int r=0; r<5; r++){
            int task = blk + r*GB;
            int ks = task / 20, nt = task % 20;
            gtask(g_A, KST, g_Wpack, NG, nt*128, ks*32,
                  g_gp + (size_t)ks*(BB*NG), NG, nullptr, nullptr, 0);
        }
        gridbar();

        // ---- P2: reduce gates + LSTM elementwise (1 warp per block, 4096 quads)
        if (tid < 32){
            int quad = blk*32 + tid;
            int b = quad>>7, jq = quad&127; int j = jq<<2;
            float4 gg[5];
#pragma unroll
            for (int c=0;c<5;c++){
                int col = c*HID + j;
                float4 x = *(const float4*)(g_xproj + (size_t)t*(BB*NG) + b*NG + col);
#pragma unroll
                for (int s=0;s<32;s++){
                    const float4 v = *(const float4*)(g_gp + (size_t)s*(BB*NG) + b*NG + col);
                    x.x+=v.x; x.y+=v.y; x.z+=v.z; x.w+=v.w;
                }
                gg[c] = x;
            }
            float4 cold = *(const float4*)(g_c + b*HID + j);
            float co[4] = {cold.x, cold.y, cold.z, cold.w};
            float cn4[4], hn4[4], f04[4];
            float iv4[4] = {gg[0].x,gg[0].y,gg[0].z,gg[0].w};
            float fv4[4] = {gg[1].x,gg[1].y,gg[1].z,gg[1].w};
            float gv4[4] = {gg[2].x,gg[2].y,gg[2].z,gg[2].w};
            float ov4[4] = {gg[3].x,gg[3].y,gg[3].z,gg[3].w};
            float n54[4] = {gg[4].x,gg[4].y,gg[4].z,gg[4].w};
#pragma unroll
            for (int e=0;e<4;e++){
                float cn = sigf(fv4[e])*co[e] + sigf(iv4[e])*tanhf(gv4[e]);
                float tc = tanhf(cn);
                cn4[e] = cn;
                hn4[e] = sigf(ov4[e])*tc;
                f04[e] = sigf(n54[e])*tc;
            }
            *(float4*)(g_c   + b*HID + j) = make_float4(cn4[0],cn4[1],cn4[2],cn4[3]);
            *(float4*)(g_A   + b*KST + HID + j) = make_float4(hn4[0],hn4[1],hn4[2],hn4[3]);
            *(float4*)(g_fr0 + b*HID + j) = make_float4(f04[0],f04[1],f04[2],f04[3]);
        }
        gridbar();

        // ---- P3: fr0@Wfr and h@Who partials (128 tasks)
        {
            int ks = blk & 15, nt = (blk>>4)&3, mat = blk>>6;
            const float* A = mat ? (g_A + HID) : g_fr0;
            int lda = mat ? KST : HID;
            const float* W = mat ? Who : Wfr;
            gtask(A, lda, W, HID, nt*128, ks*32,
                  g_p3 + (size_t)mat*(16*BB*HID) + (size_t)ks*(BB*HID), HID, nullptr, nullptr, 0);
        }
        gridbar();

        // ---- P4: fr@Wfre, hol@Whoe partials (A staged on the fly from p3)
        {
            int ks = blk & 15, nt = (blk>>4)&3, mat = blk>>6;
            const float* W = mat ? Whoe : Wfre;
            gtask(nullptr, 0, W, HID, nt*128, ks*32,
                  g_p4 + (size_t)mat*(16*BB*HID) + (size_t)ks*(BB*HID), HID,
                  g_p3 + (size_t)mat*(16*BB*HID), mat ? bho : bfr, mat ? 2 : 1);
        }
        gridbar();

        // ---- P4.5: finalize fr, hol, fre, hoe (16384 quad-tasks)
        if (tid < 128){
            int gq = blk*128 + tid;
            int arr = gq>>12, q = gq&4095;
            int b = q>>7, j = (q&127)<<2;
            const float* pb; const float* bias; int act; float* dst;
            if (arr==0){ pb=g_p3;                 bias=bfr;  act=1; dst=g_fr;  }
            else if (arr==1){ pb=g_p3+16*BB*HID;  bias=bho;  act=2; dst=g_hol; }
            else if (arr==2){ pb=g_p4;            bias=bfre; act=0; dst=g_fre; }
            else            { pb=g_p4+16*BB*HID;  bias=bhoe; act=0; dst=g_hoe; }
            float4 s = *(const float4*)(bias + j);
#pragma unroll
            for (int p=0;p<16;p++){
                const float4 v = *(const float4*)(pb + (size_t)p*(BB*HID) + b*HID + j);
                s.x+=v.x; s.y+=v.y; s.z+=v.z; s.w+=v.w;
            }
            if (act==1){ s.x=fmaxf(s.x,0.f); s.y=fmaxf(s.y,0.f); s.z=fmaxf(s.z,0.f); s.w=fmaxf(s.w,0.f); }
            else if (act==2){ s.x=tanhf(s.x); s.y=tanhf(s.y); s.z=tanhf(s.z); s.w=tanhf(s.w); }
            *(float4*)(dst + b*HID + j) = s;
        }
        gridbar();

        // ---- P5: attention scores (one warp per (b,a); 8224 warp-tasks)
        {
            int wid = tid>>5, l = tid&31;
            for (int gw = blk*8 + wid; gw < BB*NA; gw += GB*8){
                int b = gw / NA, a = gw % NA;
                const float* e   = (a==0) ? (g_fre + b*HID)
                                          : (g_ctx_embed + ((size_t)b*ATTN + (a-1))*CTXD);
                const float* hoe = g_hoe + b*HID;
                float acc = 0.f;
#pragma unroll
                for (int i=0;i<4;i++){
                    int idx = i*128 + l*4;
                    float4 ev = *(const float4*)(e + idx);
                    float4 hv = *(const float4*)(hoe + idx);
                    float4 wv = *(const float4*)(Wa + idx);
                    acc += wv.x*tanha(ev.x+hv.x);
                    acc += wv.y*tanha(ev.y+hv.y);
                    acc += wv.z*tanha(ev.z+hv.z);
                    acc += wv.w*tanha(ev.w+hv.w);
                }
#pragma unroll
                for (int off=16; off; off>>=1) acc += __shfl_xor_sync(0xffffffffu, acc, off);
                if (l == 0) g_scores[gw] = acc + ba[0];
            }
        }
        gridbar();

        // ---- P6: softmax + vis + add hol (block -> (b, quarter of h))
        {
            int b = blk>>2, half = blk&3;
            float* s_sc  = sh;         // 257 (scores -> pi)
            float* s_red = sh + 272;   // 256
            float* s_v   = sh + 544;   // 1024
            s_sc[tid] = g_scores[b*NA + tid];
            if (tid == 0) s_sc[256] = g_scores[b*NA + 256];
            __syncthreads();
            float mv = s_sc[tid];
            if (tid == 0) mv = fmaxf(mv, s_sc[256]);
            s_red[tid] = mv; __syncthreads();
            for (int st=128; st; st>>=1){ if (tid<st) s_red[tid] = fmaxf(s_red[tid], s_red[tid+st]); __syncthreads(); }
            float mx = s_red[0]; __syncthreads();
            float ev  = expf(s_sc[tid] - mx);
            float ev2 = (tid==0) ? expf(s_sc[256] - mx) : 0.f;
            s_red[tid] = ev + ev2; __syncthreads();
            for (int st=128; st; st>>=1){ if (tid<st) s_red[tid] += s_red[tid+st]; __syncthreads(); }
            float inv = 1.f / s_red[0];
            __syncthreads();
            s_sc[tid] = ev * inv;
            if (tid == 0) s_sc[256] = ev2 * inv;
            __syncthreads();
            int aa = tid>>5, hq = tid&31;
            int h = half*128 + hq*4;
            float4 acc = make_float4(0.f,0.f,0.f,0.f);
            for (int a = aa; a < NA; a += 8){
                float w = s_sc[a];
                float4 v = (a==0) ? *(const float4*)(g_fr + b*HID + h)
                                  : *(const float4*)(cnn + ((size_t)b*ATTN + (a-1))*CTXD + h);
                acc.x += w*v.x; acc.y += w*v.y; acc.z += w*v.z; acc.w += w*v.w;
            }
            *(float4*)&s_v[aa*128 + hq*4] = acc;
            __syncthreads();
            if (tid < 32){
                int hq2 = tid; int h2 = half*128 + hq2*4;
                float4 s = make_float4(0.f,0.f,0.f,0.f);
#pragma unroll
                for (int a2=0;a2<8;a2++){
                    const float4 v = *(const float4*)&s_v[a2*128 + hq2*4];
                    s.x+=v.x; s.y+=v.y; s.z+=v.z; s.w+=v.w;
                }
                const float4 ho = *(const float4*)(g_hol + b*HID + h2);
                s.x+=ho.x; s.y+=ho.y; s.z+=ho.z; s.w+=ho.w;
                *(float4*)(g_visph + b*HID + h2) = s;
            }
            __syncthreads();
        }
        gridbar();

        // ---- P7: outh partials (64 tasks)
        if (blk < 64){
            int ks = blk & 15, nt = blk>>4;
            gtask(g_visph, HID, Watt, HID, nt*128, ks*32,
                  g_p7 + (size_t)ks*(BB*HID), HID, nullptr, nullptr, 0);
        }
        gridbar();

        // ---- P7.5: finalize outh -> g_A[:, :512] and g_outh[t]
        if (tid < 32){
            int quad = blk*32 + tid;
            int b = quad>>7, j = (quad&127)<<2;
            float4 s = *(const float4*)(batt + j);
#pragma unroll
            for (int p=0;p<16;p++){
                const float4 v = *(const float4*)(g_p7 + (size_t)p*(BB*HID) + b*HID + j);
                s.x+=v.x; s.y+=v.y; s.z+=v.z; s.w+=v.w;
            }
            s.x=tanhf(s.x); s.y=tanhf(s.y); s.z=tanhf(s.z); s.w=tanhf(s.w);
            *(float4*)(g_A + b*KST + j) = s;
            *(float4*)(g_outh + (size_t)t*(BB*HID) + b*HID + j) = s;
        }
        gridbar();
    }
}

// ---------------- log_softmax + [t][b] -> [b][t] remap ----------------
__global__ void k_logsm(float* __restrict__ out){
    int r = blockIdx.x;
    int t = r >> 5, b = r & 31;
    const float* row = g_logits + (size_t)r*VOC;
    float* orow = out + ((size_t)b*TT + t)*VOC;
    __shared__ float red[256];
    int tid = threadIdx.x;
    float mx = -1e30f;
    for (int i=tid; i<VOC; i+=256) mx = fmaxf(mx, row[i]);
    red[tid] = mx; __syncthreads();
    for (int st=128; st>0; st>>=1){ if (tid<st) red[tid] = fmaxf(red[tid], red[tid+st]); __syncthreads(); }
    mx = red[0]; __syncthreads();
    float sm = 0.f;
    for (int i=tid; i<VOC; i+=256) sm += expf(row[i] - mx);
    red[tid] = sm; __syncthreads();
    for (int st=128; st>0; st>>=1){ if (tid<st) red[tid] += red[tid+st]; __syncthreads(); }
    float ls = mx + logf(red[0]);
    for (int i=tid; i<VOC; i+=256) orow[i] = row[i] - ls;
}

// ---------------- launch ----------------
extern "C" void kernel_launch(void* const* d_in, const int* in_sizes, int n_in,
                              void* d_out, int out_size){
    const float* cnn  = (const float*)d_in[0];
    const int*   seq  = (const int*)  d_in[1];
    const float* emb  = (const float*)d_in[2];
    const float* Wce  = (const float*)d_in[3];  const float* bce  = (const float*)d_in[4];
    const float* Wih  = (const float*)d_in[5];  const float* bih  = (const float*)d_in[6];
    const float* Whh  = (const float*)d_in[7];  const float* bhh  = (const float*)d_in[8];
    const float* Wi2h = (const float*)d_in[9];  const float* bi2h = (const float*)d_in[10];
    const float* Wh2h = (const float*)d_in[11]; const float* bh2h = (const float*)d_in[12];
    const float* Wfr  = (const float*)d_in[13]; const float* bfr  = (const float*)d_in[14];
    const float* Wfre = (const float*)d_in[15]; const float* bfre = (const float*)d_in[16];
    const float* Who  = (const float*)d_in[17]; const float* bho  = (const float*)d_in[18];
    const float* Whoe = (const float*)d_in[19]; const float* bhoe = (const float*)d_in[20];
    const float* Wa   = (const float*)d_in[21]; const float* ba   = (const float*)d_in[22];
    const float* Watt = (const float*)d_in[23]; const float* batt = (const float*)d_in[24];
    const float* Wlog = (const float*)d_in[25]; const float* blog = (const float*)d_in[26];
    float* out = (float*)d_out;

    k_init<<<192, 256>>>();
    k_packW<<<(KST*NG)/256, 256>>>(Wih, Whh, Wi2h, Wh2h);
    k_packX<<<(EMBD*NG)/256, 256>>>(Wih, Wi2h, bih, bhh, bi2h, bh2h);
    k_gather<<<(TT*BB*EMBD)/256, 256>>>(seq, emb);
    gemm_big<<<dim3(CTXD/64, (BB*ATTN)/64), 256>>>(0, cnn, Wce, bce, CTXD, CTXD, 1);
    gemm_big<<<dim3(NG/64, (TT*BB)/64), 256>>>(1, nullptr, nullptr, nullptr, NG, EMBD, 0);

    persist_kernel<<<GB, 256>>>(cnn, Wfr, bfr, Who, bho, Wfre, bfre, Whoe, bhoe,
                                Wa, ba, Watt, batt);

    gemm_big<<<dim3((VOC+63)/64, (TT*BB)/64), 256>>>(2, nullptr, Wlog, blog, VOC, HID, 0);
    k_logsm<<<TT*BB, 256>>>(out);
}